// round 14
// baseline (speedup 1.0000x reference)
#include <cuda_runtime.h>
#include <cstdint>

#define HID 512
#define H6  3072
#define BB  16
#define TT  1000
#define DTC 0.01f
#define NTHR 256
#define NCTA 148

#define W_TOT 2621440
// output layout (floats): out | hn_last | rnn_out | x_last | x_out
#define OUT_OFF   0ULL
#define HN_OFF    16000ULL
#define RNN_OFF   65152ULL
#define XLAST_OFF 49217152ULL
#define XOUT_OFF  49266304ULL

// -------- persistent device state ----------
__device__ __align__(16) float g_Wt[W_TOT];      // packed effective W, per region [Kcat][512]
__device__ __align__(16) float g_h[8][H6 * BB];  // h ring buffer, layout [j][b]
__device__ float g_v[HID];                       // relu(fc1[alm]) @ relu(fc2)
__device__ unsigned g_cnt[768];                  // per-region counters, 512B apart (idx r*128)

__host__ __device__ constexpr int roff_of(int r) {
    return r==0?0 : r==1?786432 : r==2?1048576 : r==3?1310720 : r==4?1835008 : 2097152;
}
// CTAs per region: str=48, gpe=8, stn=16, snr=28, thal=16, alm=32
__host__ __device__ constexpr unsigned ncta_of(int r) {
    return r==0?48u : r==1?8u : r==2?16u : r==3?28u : r==4?16u : 32u;
}

// ---------------- PTX helpers ----------------
__device__ __forceinline__ void cp16(unsigned dst_s, const void* src) {
    asm volatile("cp.async.cg.shared.global [%0], [%1], 16;" :: "r"(dst_s), "l"(src) : "memory");
}
#define CP_COMMIT() asm volatile("cp.async.commit_group;" ::: "memory")
#define CP_WAIT(N)  asm volatile("cp.async.wait_group %0;" :: "n"(N) : "memory")
__device__ __forceinline__ unsigned ld_acq(const unsigned* p) {
    unsigned v;
    asm volatile("ld.acquire.gpu.global.u32 %0, [%1];" : "=r"(v) : "l"(p) : "memory");
    return v;
}
__device__ __forceinline__ void red_rel(unsigned* p) {
    asm volatile("red.release.gpu.global.add.u32 [%0], %1;" :: "l"(p), "r"(1u) : "memory");
}
#define FMA2(acc, w, h) asm("fma.rn.f32x2 %0, %1, %2, %0;" : "+l"(acc) : "l"(w), "l"(h))
#define ADD2(acc, v)    asm("add.rn.f32x2 %0, %0, %1;"     : "+l"(acc) : "l"(v))
#define PACK2(d, f)     asm("mov.b64 %0, {%1, %1};"        : "=l"(d)   : "f"(f))
#define UNPK2(lo, hi, v) asm("mov.b64 {%0, %1}, %2;" : "=f"(lo), "=f"(hi) : "l"(v))

// ---------------- prep: build W_eff, init h0, v, reset counters ----------
__global__ void prep_kernel(
    const float* __restrict__ hn,
    const float* __restrict__ thal2alm_w, const float* __restrict__ thal2str_w,
    const float* __restrict__ alm2alm_w,  const float* __restrict__ alm2str_w,
    const float* __restrict__ str2snr_w,  const float* __restrict__ str2gpe_w,
    const float* __restrict__ gpe2stn_w,  const float* __restrict__ stn2snr_w,
    const float* __restrict__ snr2thal_w, const float* __restrict__ fc1,
    const float* __restrict__ fc2,        const float* __restrict__ str2str_fixed)
{
    int idx = blockIdx.x * blockDim.x + threadIdx.x;
    if (idx < 768) g_cnt[idx] = 0u;
    if (idx < W_TOT) {
        int r;
        if (idx < 786432) r = 0;
        else if (idx < 1048576) r = 1;
        else if (idx < 1310720) r = 2;
        else if (idx < 1835008) r = 3;
        else if (idx < 2097152) r = 4;
        else r = 5;
        int rem  = idx - roff_of(r);
        int kcat = rem >> 9;
        int j    = rem & 511;
        int seg  = kcat >> 9;
        int k    = kcat & 511;
        int wi = j * HID + k;
        float val;
        if (r == 0) {
            if (seg == 0)      val = -str2str_fixed[wi];
            else if (seg == 1) val = (j >= 128 && j < 384) ? fmaxf(thal2str_w[wi], 0.f) : 0.f;
            else               val = (k < 359) ? fmaxf(alm2str_w[wi], 0.f) : 0.f;
        } else if (r == 1) {
            val = (k >= 256) ? -fmaxf(str2gpe_w[wi], 0.f) : 0.f;
        } else if (r == 2) {
            val = -fmaxf(gpe2stn_w[wi], 0.f);
        } else if (r == 3) {
            val = (seg == 0) ? ((k < 256) ? -fmaxf(str2snr_w[wi], 0.f) : 0.f)
                             : fmaxf(stn2snr_w[wi], 0.f);
        } else if (r == 4) {
            val = -fmaxf(snr2thal_w[wi], 0.f);
        } else {
            val = (seg == 0) ? fmaxf(thal2alm_w[wi], 0.f)
                             : fmaxf(alm2alm_w[wi], 0.f) * ((k < 359) ? 1.f : -1.f);
        }
        g_Wt[idx] = val;
    } else if (idx < W_TOT + H6 * BB) {
        int e = idx - W_TOT;
        int j = e >> 4, b = e & 15;
        g_h[0][e] = hn[b * H6 + j];
    } else if (idx < W_TOT + H6 * BB + HID) {
        int j = idx - (W_TOT + H6 * BB);
        const float* f1 = fc1 + (size_t)(5 * HID + j) * HID;
        float s = 0.f;
        for (int m = 0; m < HID; m++) s += fmaxf(f1[m], 0.f) * fmaxf(fc2[m], 0.f);
        g_v[j] = s;
    }
}

// ---------------- persistent recurrence, templated per region ------------
// Weights live in REGISTERS (constant across steps). Segments:
// (SRC region, W orig-kcat offset, L length). WPT0/WPT12 = per-thread k counts.
template<int RG, int R, int S, int NSEG, int SH,
         int S0, int W0, int L0, int WPT0,
         int S1, int W1, int L1,
         int S2, int W2, int L2, int WPT12>
__device__ __forceinline__ void run_region(
    int j0, const float* __restrict__ inp, const float* __restrict__ inhib,
    const float* __restrict__ inp_w, float* __restrict__ d_out, float* sm)
{
    const int tid = threadIdx.x;
    constexpr int L12  = L1 + L2;
    constexpr int LTOT = L0 + L12;
    constexpr int DEP  = S >> SH;          // sRed depth after shuffle pre-reduce

    float* sH   = sm;                      // (LTOT+64)*16 floats (64 k-entries of zero pad)
    float* sRed = sH + (LTOT + 64) * 16;   // DEP*R*16
    float* sInh = sRed + DEP * R * 16;     // R*16
    float* sWi  = sInh + R * 16;           // R*4
    float* sInp = sWi + R * 4;             // 64

    // ---- zero sH (pad zone must stay 0; live zone overwritten each step) --
    for (int i = tid; i < (LTOT + 64) * 16; i += NTHR) sH[i] = 0.f;

    for (int i = tid; i < R * 16; i += NTHR) {
        int jj = i >> 4, b = i & 15; int jrow = j0 + jj;
        sInh[i] = (jrow < 512) ? inhib[b * H6 + RG * HID + jrow] : 0.f;
    }
    for (int i = tid; i < R * 4; i += NTHR) {
        int jj = i >> 2, ii = i & 3; int jrow = j0 + jj;
        int jg = RG * HID + jrow;
        float st = (RG == 0 && jrow < 512 && jg >= 128 && jg < 384) ? 1.f : 0.f;
        sWi[i] = st * fmaxf(inp_w[ii * H6 + (jg < H6 ? jg : 0)], 0.f);
    }
    const float tonic = (RG == 1 || RG == 2 || RG == 4) ? 1.f : 0.f;

    // ---- thread roles ----
    const int jt = tid % R;
    const int s  = tid / R;
    const bool act = s < S;
    const int jrow_t = j0 + jt;

    // ---- weights into registers (zero-padded out of range) ----
    float w0r[WPT0];
    #pragma unroll
    for (int k = 0; k < WPT0; k++) {
        int kk = s * WPT0 + k;
        w0r[k] = (act && kk < L0 && jrow_t < 512)
                 ? g_Wt[roff_of(RG) + ((W0 + kk) << 9) + jrow_t] : 0.f;
    }
    float w1r[(NSEG > 1) ? WPT12 : 1];
    if constexpr (NSEG > 1) {
        #pragma unroll
        for (int k = 0; k < WPT12; k++) {
            int kk = s * WPT12 + k;
            int kc = (kk < L1) ? (W1 + kk) : (W2 + kk - L1);
            w1r[k] = (act && kk < L12 && jrow_t < 512)
                     ? g_Wt[roff_of(RG) + (kc << 9) + jrow_t] : 0.f;
        }
    }

    // ---- update-thread identity + h kept in registers ----
    const int jr = tid >> 2, q = tid & 3;
    const int jrow_u = j0 + jr;
    const bool upd = (tid < 4 * R) && (jrow_u < 512);
    const int jg_u = RG * HID + jrow_u;
    float4 hown = make_float4(0.f, 0.f, 0.f, 0.f);
    if (upd) hown = *((const float4*)(g_h[0] + (size_t)jg_u * 16) + q);

    const unsigned sHb = (unsigned)__cvta_generic_to_shared(sH);
    __syncthreads();

    for (int t = 0; t < TT; t++) {
        const float* hb = g_h[t & 7];
        const unsigned ut = (unsigned)t;

        // ---- inp staging first: independent of counters ----
        if (RG == 0 && tid < 64)
            sInp[tid] = __ldg(inp + (size_t)(tid >> 2) * TT * 4 + t * 4 + (tid & 3));

        // ---- all-thread polls (empirically best detect), nanosleep backoff --
        {
            const unsigned tgt = ncta_of(S0) * ut;
            if (ld_acq(&g_cnt[S0 * 128]) < tgt)
                while (ld_acq(&g_cnt[S0 * 128]) < tgt) __nanosleep(40);
        }
        if constexpr (NSEG > 1) {
            const unsigned tgt = ncta_of(S1) * ut;
            if (ld_acq(&g_cnt[S1 * 128]) < tgt)
                while (ld_acq(&g_cnt[S1 * 128]) < tgt) __nanosleep(40);
        }
        if constexpr (NSEG > 2) {
            const unsigned tgt = ncta_of(S2) * ut;
            if (ld_acq(&g_cnt[S2 * 128]) < tgt)
                while (ld_acq(&g_cnt[S2 * 128]) < tgt) __nanosleep(40);
        }

        // ---- stage seg0 (group 1) ----
        {
            const float4* sp = (const float4*)(hb + ((S0 << 9) + (W0 & 511)) * 16);
            #pragma unroll
            for (int i = 0; i < L0 / 64; i++)
                cp16(sHb + (unsigned)(i * NTHR + tid) * 16u, sp + i * NTHR + tid);
            CP_COMMIT();
        }
        // ---- stage seg1 + seg2 (group 2) ----
        if constexpr (NSEG > 1) {
            const float4* sp = (const float4*)(hb + ((S1 << 9) + (W1 & 511)) * 16);
            const unsigned dst = sHb + (unsigned)L0 * 64u;
            #pragma unroll
            for (int i = 0; i < L1 / 64; i++)
                cp16(dst + (unsigned)(i * NTHR + tid) * 16u, sp + i * NTHR + tid);
            if constexpr (NSEG > 2) {
                const float4* sp2 = (const float4*)(hb + ((S2 << 9) + (W2 & 511)) * 16);
                const unsigned dst2 = sHb + (unsigned)(L0 + L1) * 64u;
                #pragma unroll
                for (int i = 0; i < L2 / 64; i++)
                    cp16(dst2 + (unsigned)(i * NTHR + tid) * 16u, sp2 + i * NTHR + tid);
            }
            CP_COMMIT();
        }

        // ---- compute: fully unrolled, weights in registers ----
        unsigned long long a[8] = {0, 0, 0, 0, 0, 0, 0, 0};
        const ulonglong2* sH2 = (const ulonglong2*)sH;

        if constexpr (NSEG > 1) CP_WAIT(1); else CP_WAIT(0);
        __syncthreads();
        {
            const ulonglong2* ph = sH2 + (size_t)(s * WPT0) * 4;
            #pragma unroll
            for (int k = 0; k < WPT0; k++) {
                unsigned long long ww; PACK2(ww, w0r[k]);
                ulonglong2 u0 = ph[k*4+0], u1 = ph[k*4+1], u2 = ph[k*4+2], u3 = ph[k*4+3];
                FMA2(a[0], ww, u0.x); FMA2(a[1], ww, u0.y);
                FMA2(a[2], ww, u1.x); FMA2(a[3], ww, u1.y);
                FMA2(a[4], ww, u2.x); FMA2(a[5], ww, u2.y);
                FMA2(a[6], ww, u3.x); FMA2(a[7], ww, u3.y);
            }
        }
        if constexpr (NSEG > 1) {
            CP_WAIT(0);
            __syncthreads();
            const ulonglong2* ph = sH2 + (size_t)(L0 + s * WPT12) * 4;
            #pragma unroll
            for (int k = 0; k < WPT12; k++) {
                unsigned long long ww; PACK2(ww, w1r[k]);
                ulonglong2 u0 = ph[k*4+0], u1 = ph[k*4+1], u2 = ph[k*4+2], u3 = ph[k*4+3];
                FMA2(a[0], ww, u0.x); FMA2(a[1], ww, u0.y);
                FMA2(a[2], ww, u1.x); FMA2(a[3], ww, u1.y);
                FMA2(a[4], ww, u2.x); FMA2(a[5], ww, u2.y);
                FMA2(a[6], ww, u3.x); FMA2(a[7], ww, u3.y);
            }
        }

        // ---- warp-shuffle pre-reduce over s within warp, then store ----
        #pragma unroll
        for (int st = 0; st < SH; st++) {
            const unsigned msk = (unsigned)R << st;
            #pragma unroll
            for (int i = 0; i < 8; i++) {
                unsigned long long o = __shfl_xor_sync(0xffffffffu, a[i], msk);
                ADD2(a[i], o);
            }
        }
        if (act && ((SH == 0) || ((s & ((1 << SH) - 1)) == 0))) {
            ulonglong2* rp = (ulonglong2*)sRed + ((size_t)(s >> SH) * R + jt) * 4;
            rp[0] = make_ulonglong2(a[0], a[1]); rp[1] = make_ulonglong2(a[2], a[3]);
            rp[2] = make_ulonglong2(a[4], a[5]); rp[3] = make_ulonglong2(a[6], a[7]);
        }
        __syncthreads();

        // ---- reduce across DEP + state update (h only; d_out deferred) ----
        if (upd) {
            unsigned long long x0 = 0, x1 = 0, y0 = 0, y1 = 0;
            const ulonglong2* rp = (const ulonglong2*)sRed + (size_t)jr * 4 + q;
            #pragma unroll
            for (int ss = 0; ss + 1 < DEP; ss += 2) {
                ulonglong2 v0 = rp[(size_t)ss * R * 4];
                ulonglong2 v1 = rp[(size_t)(ss + 1) * R * 4];
                ADD2(x0, v0.x); ADD2(y0, v0.y);
                ADD2(x1, v1.x); ADD2(y1, v1.y);
            }
            if constexpr (DEP & 1) {
                ulonglong2 v0 = rp[(size_t)(DEP - 1) * R * 4];
                ADD2(x0, v0.x); ADD2(y0, v0.y);
            }
            ADD2(x0, x1); ADD2(y0, y1);
            float ac[4];
            UNPK2(ac[0], ac[1], x0); UNPK2(ac[2], ac[3], y0);
            float w0 = 0.f, w1 = 0.f, w2 = 0.f, w3 = 0.f;
            if (RG == 0) { w0 = sWi[jr*4]; w1 = sWi[jr*4+1]; w2 = sWi[jr*4+2]; w3 = sWi[jr*4+3]; }
            float* hp = &hown.x;
            #pragma unroll
            for (int i2 = 0; i2 < 4; i2++) {
                const int b = q * 4 + i2;
                float d = sInh[jr * 16 + b] + tonic;
                if (RG == 0)
                    d += w0 * sInp[b*4] + w1 * sInp[b*4+1] + w2 * sInp[b*4+2] + w3 * sInp[b*4+3];
                float v = hp[i2] * (1.f - DTC) + DTC * (ac[i2] + d);
                hp[i2] = fmaxf(v, 0.f);
            }
            __stcg((float4*)(g_h[(t + 1) & 7] + (size_t)jg_u * 16) + q, hown);
        }
        __syncthreads();
        // single fence + publish
        if (tid == 0) { __threadfence(); red_rel(&g_cnt[RG * 128]); }

        // ---- deferred d_out writes (off the inter-region critical path) ----
        if (upd) {
            const float* hp = &hown.x;
            #pragma unroll
            for (int i2 = 0; i2 < 4; i2++) {
                const int b = q * 4 + i2;
                d_out[RNN_OFF + ((size_t)b * TT + t) * H6 + jg_u] = hp[i2];
                if (t == TT - 1) d_out[HN_OFF + (size_t)b * H6 + jg_u] = hp[i2];
            }
        }
    }
}

__global__ void __launch_bounds__(NTHR, 1) rnn_persist(
    const float* __restrict__ inp, const float* __restrict__ inhib,
    const float* __restrict__ inp_w, float* __restrict__ d_out)
{
    extern __shared__ float sm[];
    const int b = blockIdx.x;
    //            RG  R   S  NSEG SH  S0 W0  L0 WPT0  S1  W1  L1   S2  W2   L2 WPT12
    if (b < 32) {       // str rows 128..383 (str + thal + alm)
        run_region<0,  8, 32, 3, 2,  0, 0, 512, 16,  4, 512, 512,  5, 1024, 384, 28>(
            128 + b * 8, inp, inhib, inp_w, d_out, sm);
    } else if (b < 48) { // str rows 0..127 & 384..511 (str + alm)
        int c = b - 32;
        int j0 = (c < 8) ? c * 16 : 384 + (c - 8) * 16;
        run_region<0, 16, 16, 2, 1,  0, 0, 512, 32,  5, 1024, 384,  0, 0, 0, 24>(
            j0, inp, inhib, inp_w, d_out, sm);
    } else if (b < 56) { // gpe (str[256:512])
        run_region<1, 64,  4, 1, 0,  0, 256, 256, 64,  0, 0, 0,  0, 0, 0, 1>(
            (b - 48) * 64, inp, inhib, inp_w, d_out, sm);
    } else if (b < 72) { // stn (gpe)
        run_region<2, 32,  8, 1, 0,  1, 0, 512, 64,  0, 0, 0,  0, 0, 0, 1>(
            (b - 56) * 32, inp, inhib, inp_w, d_out, sm);
    } else if (b < 100) { // snr (str[0:256] + stn)
        run_region<3, 19, 13, 2, 0,  0, 0, 256, 20,  2, 512, 512,  0, 0, 0, 40>(
            (b - 72) * 19, inp, inhib, inp_w, d_out, sm);
    } else if (b < 116) { // thal (snr)
        run_region<4, 32,  8, 1, 0,  3, 0, 512, 64,  0, 0, 0,  0, 0, 0, 1>(
            (b - 100) * 32, inp, inhib, inp_w, d_out, sm);
    } else {             // alm (thal + alm)
        run_region<5, 16, 16, 2, 1,  4, 0, 512, 32,  5, 512, 512,  0, 0, 0, 32>(
            (b - 116) * 16, inp, inhib, inp_w, d_out, sm);
    }
}

// ---------------- epilogue: out = sigmoid(alm_h . v) ---------------------
__global__ void out_kernel(float* __restrict__ d_out)
{
    int gw   = (blockIdx.x * blockDim.x + threadIdx.x) >> 5;
    int lane = threadIdx.x & 31;
    if (gw >= BB * TT) return;
    const float4* row4 = (const float4*)(d_out + RNN_OFF + (size_t)gw * H6 + 5 * HID);
    const float4* v4   = (const float4*)g_v;
    float sum = 0.f;
    #pragma unroll
    for (int j = lane; j < 128; j += 32) {
        float4 rv = row4[j], vv = v4[j];
        sum = fmaf(rv.x, vv.x, fmaf(rv.y, vv.y, fmaf(rv.z, vv.z, fmaf(rv.w, vv.w, sum))));
    }
    #pragma unroll
    for (int o = 16; o; o >>= 1) sum += __shfl_xor_sync(0xffffffffu, sum, o);
    if (lane == 0) d_out[gw] = 1.f / (1.f + expf(-sum));
}

// ---------------- epilogue: x_out / x_last broadcast copy ----------------
__global__ void x_kernel(const float* __restrict__ x, float* __restrict__ d_out)
{
    const float4* x4 = (const float4*)x;
    float4* o4 = (float4*)d_out;
    const size_t total = 12288 + 12288000;
    for (size_t i = blockIdx.x * (size_t)blockDim.x + threadIdx.x; i < total;
         i += (size_t)gridDim.x * blockDim.x) {
        if (i < 12288) {
            o4[XLAST_OFF / 4 + i] = x4[i];
        } else {
            size_t e = i - 12288;
            int j4 = (int)(e % 768);
            int bt = (int)(e / 768);
            int bq = bt / TT;
            o4[XOUT_OFF / 4 + e] = x4[bq * 768 + j4];
        }
    }
}

extern "C" void kernel_launch(void* const* d_in, const int* in_sizes, int n_in,
                              void* d_out_v, int out_size)
{
    const float* inp        = (const float*)d_in[0];
    const float* hn         = (const float*)d_in[1];
    const float* x          = (const float*)d_in[2];
    const float* inhib      = (const float*)d_in[3];
    const float* thal2alm_w = (const float*)d_in[5];
    const float* thal2str_w = (const float*)d_in[6];
    const float* alm2alm_w  = (const float*)d_in[7];
    const float* alm2str_w  = (const float*)d_in[8];
    const float* str2snr_w  = (const float*)d_in[9];
    const float* str2gpe_w  = (const float*)d_in[10];
    const float* stn2snr_w  = (const float*)d_in[12];
    const float* gpe2stn_w  = (const float*)d_in[11];
    const float* snr2thal_w = (const float*)d_in[13];
    const float* inp_w      = (const float*)d_in[14];
    const float* fc1        = (const float*)d_in[15];
    const float* fc2        = (const float*)d_in[16];
    const float* fixed      = (const float*)d_in[17];
    float* d_out = (float*)d_out_v;

    // max smem: str-A = (1472*16 + 8*8*16 + 128 + 32 + 64) * 4 = 99,264 B
    static int smem_set = 0;
    if (!smem_set) {
        cudaFuncSetAttribute(rnn_persist, cudaFuncAttributeMaxDynamicSharedMemorySize, 100352);
        smem_set = 1;
    }

    x_kernel<<<4096, 256>>>(x, d_out);

    int prep_total = W_TOT + H6 * BB + HID;
    prep_kernel<<<(prep_total + 255) / 256, 256>>>(
        hn, thal2alm_w, thal2str_w, alm2alm_w, alm2str_w, str2snr_w,
        str2gpe_w, gpe2stn_w, stn2snr_w, snr2thal_w, fc1, fc2, fixed);

    rnn_persist<<<NCTA, NTHR, 100352>>>(inp, inhib, inp_w, d_out);

    out_kernel<<<(BB * TT * 32 + 255) / 256, 256>>>(d_out);
}

// round 16
// speedup vs baseline: 1.0789x; 1.0789x over previous
#include <cuda_runtime.h>
#include <cstdint>

#define HID 512
#define H6  3072
#define BB  16
#define TT  1000
#define DTC 0.01f
#define NTHR 256
#define NCTA 148

#define W_TOT 2621440
// output layout (floats): out | hn_last | rnn_out | x_last | x_out
#define OUT_OFF   0ULL
#define HN_OFF    16000ULL
#define RNN_OFF   65152ULL
#define XLAST_OFF 49217152ULL
#define XOUT_OFF  49266304ULL

// -------- persistent device state ----------
__device__ __align__(16) float g_Wt[W_TOT];      // packed effective W, per region [Kcat][512]
__device__ __align__(16) float g_h[8][H6 * BB];  // h ring buffer, layout [j][b]
__device__ float g_v[HID];                       // relu(fc1[alm]) @ relu(fc2)
// counters, 512B apart. ids: 0=str rows 0-255, 6=str rows 256-511,
// 1=gpe, 2=stn, 3=snr, 4=thal, 5=alm
__device__ unsigned g_cnt[1024];

__host__ __device__ constexpr int roff_of(int r) {
    return r==0?0 : r==1?786432 : r==2?1048576 : r==3?1310720 : r==4?1835008 : 2097152;
}
// arrivals per counter id per step
__host__ __device__ constexpr unsigned arr_of(int cid) {
    return cid==0?24u : cid==6?24u : cid==1?8u : cid==2?16u : cid==3?28u : cid==4?16u : 32u;
}

// ---------------- PTX helpers ----------------
__device__ __forceinline__ void cp16(unsigned dst_s, const void* src) {
    asm volatile("cp.async.cg.shared.global [%0], [%1], 16;" :: "r"(dst_s), "l"(src) : "memory");
}
#define CP_COMMIT() asm volatile("cp.async.commit_group;" ::: "memory")
#define CP_WAIT(N)  asm volatile("cp.async.wait_group %0;" :: "n"(N) : "memory")
__device__ __forceinline__ unsigned ld_acq(const unsigned* p) {
    unsigned v;
    asm volatile("ld.acquire.gpu.global.u32 %0, [%1];" : "=r"(v) : "l"(p) : "memory");
    return v;
}
__device__ __forceinline__ void red_rel(unsigned* p) {
    asm volatile("red.release.gpu.global.add.u32 [%0], %1;" :: "l"(p), "r"(1u) : "memory");
}
#define FMA2(acc, w, h) asm("fma.rn.f32x2 %0, %1, %2, %0;" : "+l"(acc) : "l"(w), "l"(h))
#define ADD2(acc, v)    asm("add.rn.f32x2 %0, %0, %1;"     : "+l"(acc) : "l"(v))
#define PACK2(d, f)     asm("mov.b64 %0, {%1, %1};"        : "=l"(d)   : "f"(f))
#define UNPK2(lo, hi, v) asm("mov.b64 {%0, %1}, %2;" : "=f"(lo), "=f"(hi) : "l"(v))

// ---------------- prep: build W_eff, init h0, v, reset counters ----------
__global__ void prep_kernel(
    const float* __restrict__ hn,
    const float* __restrict__ thal2alm_w, const float* __restrict__ thal2str_w,
    const float* __restrict__ alm2alm_w,  const float* __restrict__ alm2str_w,
    const float* __restrict__ str2snr_w,  const float* __restrict__ str2gpe_w,
    const float* __restrict__ gpe2stn_w,  const float* __restrict__ stn2snr_w,
    const float* __restrict__ snr2thal_w, const float* __restrict__ fc1,
    const float* __restrict__ fc2,        const float* __restrict__ str2str_fixed)
{
    int idx = blockIdx.x * blockDim.x + threadIdx.x;
    if (idx < 1024) g_cnt[idx] = 0u;
    if (idx < W_TOT) {
        int r;
        if (idx < 786432) r = 0;
        else if (idx < 1048576) r = 1;
        else if (idx < 1310720) r = 2;
        else if (idx < 1835008) r = 3;
        else if (idx < 2097152) r = 4;
        else r = 5;
        int rem  = idx - roff_of(r);
        int kcat = rem >> 9;
        int j    = rem & 511;
        int seg  = kcat >> 9;
        int k    = kcat & 511;
        int wi = j * HID + k;
        float val;
        if (r == 0) {
            if (seg == 0)      val = -str2str_fixed[wi];
            else if (seg == 1) val = (j >= 128 && j < 384) ? fmaxf(thal2str_w[wi], 0.f) : 0.f;
            else               val = (k < 359) ? fmaxf(alm2str_w[wi], 0.f) : 0.f;
        } else if (r == 1) {
            val = (k >= 256) ? -fmaxf(str2gpe_w[wi], 0.f) : 0.f;
        } else if (r == 2) {
            val = -fmaxf(gpe2stn_w[wi], 0.f);
        } else if (r == 3) {
            val = (seg == 0) ? ((k < 256) ? -fmaxf(str2snr_w[wi], 0.f) : 0.f)
                             : fmaxf(stn2snr_w[wi], 0.f);
        } else if (r == 4) {
            val = -fmaxf(snr2thal_w[wi], 0.f);
        } else {
            val = (seg == 0) ? fmaxf(thal2alm_w[wi], 0.f)
                             : fmaxf(alm2alm_w[wi], 0.f) * ((k < 359) ? 1.f : -1.f);
        }
        g_Wt[idx] = val;
    } else if (idx < W_TOT + H6 * BB) {
        int e = idx - W_TOT;
        int j = e >> 4, b = e & 15;
        g_h[0][e] = hn[b * H6 + j];
    } else if (idx < W_TOT + H6 * BB + HID) {
        int j = idx - (W_TOT + H6 * BB);
        const float* f1 = fc1 + (size_t)(5 * HID + j) * HID;
        float s = 0.f;
        for (int m = 0; m < HID; m++) s += fmaxf(f1[m], 0.f) * fmaxf(fc2[m], 0.f);
        g_v[j] = s;
    }
}

// ---------------- inner dot-product over one contiguous range ------------
template<int R>
__device__ __forceinline__ void dot_seg(const float* __restrict__ sWt,
    const ulonglong2* __restrict__ sH2, int jt, int coff, int klo, int khi,
    unsigned long long* a)
{
    const float* pw = sWt + (size_t)(coff + klo) * R + jt;
    const ulonglong2* ph = sH2 + (size_t)(coff + klo) * 4;
    #pragma unroll 4
    for (int k = klo; k < khi; k++) {
        float w = *pw; pw += R;
        unsigned long long ww; PACK2(ww, w);
        ulonglong2 u0 = ph[0], u1 = ph[1], u2 = ph[2], u3 = ph[3]; ph += 4;
        FMA2(a[0], ww, u0.x); FMA2(a[1], ww, u0.y);
        FMA2(a[2], ww, u1.x); FMA2(a[3], ww, u1.y);
        FMA2(a[4], ww, u2.x); FMA2(a[5], ww, u2.y);
        FMA2(a[6], ww, u3.x); FMA2(a[7], ww, u3.y);
    }
}

// ---------------- all-thread poll on one counter -------------------------
__device__ __forceinline__ void poll_cnt(int cid, unsigned t) {
    const unsigned tgt = arr_of(cid) * t;
    if (ld_acq(&g_cnt[cid * 128]) < tgt)
        while (ld_acq(&g_cnt[cid * 128]) < tgt) __nanosleep(40);
}

// ---------------- persistent recurrence, templated per region ------------
// Segments: (counter C, SRC region S, W orig-kcat offset, L length).
// seg0 is the CRITICAL segment (self-loop where one exists): polled+staged first.
// C0B: optional second counter gating seg0 (99 = none).
template<int RG, int R, int S, int K, int NSEG,
         int C0A, int C0B, int S0, int W0, int L0,
         int C1,  int S1,  int W1, int L1,
         int C2,  int S2,  int W2, int L2>
__device__ __forceinline__ void run_region(
    int j0, int pub, const float* __restrict__ inp, const float* __restrict__ inhib,
    const float* __restrict__ inp_w, float* __restrict__ d_out, float* sm)
{
    const int tid = threadIdx.x;

    float* sWt  = sm;                      // K*R  [k][jj]
    float* sH   = sWt + K * R;             // K*16 [k][b]
    float* sRed = sH + K * 16;             // S*R*16
    float* sInh = sRed + S * R * 16;       // R*16
    float* sWi  = sInh + R * 16;           // R*4
    float* sInp = sWi + R * 4;             // 64

    // ---- one-time weight fills (per segment, concat layout) ----
    for (int i = tid; i < L0 * R; i += NTHR) {
        int k = i / R, jj = i - k * R; int jrow = j0 + jj;
        sWt[(size_t)k * R + jj] = (jrow < 512) ? g_Wt[roff_of(RG) + ((W0 + k) << 9) + jrow] : 0.f;
    }
    if constexpr (NSEG > 1)
    for (int i = tid; i < L1 * R; i += NTHR) {
        int k = i / R, jj = i - k * R; int jrow = j0 + jj;
        sWt[(size_t)(L0 + k) * R + jj] = (jrow < 512) ? g_Wt[roff_of(RG) + ((W1 + k) << 9) + jrow] : 0.f;
    }
    if constexpr (NSEG > 2)
    for (int i = tid; i < L2 * R; i += NTHR) {
        int k = i / R, jj = i - k * R; int jrow = j0 + jj;
        sWt[(size_t)(L0 + L1 + k) * R + jj] = (jrow < 512) ? g_Wt[roff_of(RG) + ((W2 + k) << 9) + jrow] : 0.f;
    }
    for (int i = tid; i < R * 16; i += NTHR) {
        int jj = i >> 4, b = i & 15; int jrow = j0 + jj;
        sInh[i] = (jrow < 512) ? inhib[b * H6 + RG * HID + jrow] : 0.f;
    }
    for (int i = tid; i < R * 4; i += NTHR) {
        int jj = i >> 2, ii = i & 3; int jrow = j0 + jj;
        int jg = RG * HID + jrow;
        float st = (RG == 0 && jrow < 512 && jg >= 128 && jg < 384) ? 1.f : 0.f;
        sWi[i] = st * fmaxf(inp_w[ii * H6 + (jg < H6 ? jg : 0)], 0.f);
    }
    const float tonic = (RG == 1 || RG == 2 || RG == 4) ? 1.f : 0.f;

    // ---- update-thread identity + h kept in registers ----
    const int jr = tid >> 2, q = tid & 3;
    const int jrow_u = j0 + jr;
    const bool upd = (tid < 4 * R) && (jrow_u < 512);
    const int jg_u = RG * HID + jrow_u;
    float4 hown = make_float4(0.f, 0.f, 0.f, 0.f);
    if (upd) hown = *((const float4*)(g_h[0] + (size_t)jg_u * 16) + q);

    const unsigned sHb = (unsigned)__cvta_generic_to_shared(sH);
    const int jt = tid % R;
    const int s  = tid / R;
    const bool act = s < S;
    const int L12 = L1 + L2;               // merged tail range
    const int klo0 = (s * L0) / S,  khi0 = ((s + 1) * L0) / S;
    const int klo1 = (s * L12) / S, khi1 = ((s + 1) * L12) / S;

    __syncthreads();

    for (int t = 0; t < TT; t++) {
        const float* hb = g_h[t & 7];
        const unsigned ut = (unsigned)t;

        // ---- inp staging first: independent of counters ----
        if (RG == 0 && tid < 64)
            sInp[tid] = __ldg(inp + (size_t)(tid >> 2) * TT * 4 + t * 4 + (tid & 3));

        // ---- CRITICAL seg0: poll its counter(s), stage immediately ----
        poll_cnt(C0A, ut);
        if constexpr (C0B < 99) poll_cnt(C0B, ut);
        {
            const float4* sp = (const float4*)(hb + ((S0 << 9) + (W0 & 511)) * 16);
            #pragma unroll
            for (int i = 0; i < L0 / 64; i++)
                cp16(sHb + (unsigned)(i * NTHR + tid) * 16u, sp + i * NTHR + tid);
            CP_COMMIT();
        }
        // ---- non-critical segs: poll AFTER seg0 is in flight ----
        if constexpr (NSEG > 1) {
            poll_cnt(C1, ut);
            const float4* sp = (const float4*)(hb + ((S1 << 9) + (W1 & 511)) * 16);
            const unsigned dst = sHb + (unsigned)L0 * 64u;
            #pragma unroll
            for (int i = 0; i < L1 / 64; i++)
                cp16(dst + (unsigned)(i * NTHR + tid) * 16u, sp + i * NTHR + tid);
            if constexpr (NSEG > 2) {
                poll_cnt(C2, ut);
                const float4* sp2 = (const float4*)(hb + ((S2 << 9) + (W2 & 511)) * 16);
                const unsigned dst2 = sHb + (unsigned)(L0 + L1) * 64u;
                #pragma unroll
                for (int i = 0; i < L2 / 64; i++)
                    cp16(dst2 + (unsigned)(i * NTHR + tid) * 16u, sp2 + i * NTHR + tid);
            }
            CP_COMMIT();
        }

        // ---- compute: seg0 while group 2 lands, then merged tail ----
        unsigned long long a[8] = {0, 0, 0, 0, 0, 0, 0, 0};
        const ulonglong2* sH2 = (const ulonglong2*)sH;

        if constexpr (NSEG > 1) CP_WAIT(1); else CP_WAIT(0);
        __syncthreads();
        if (act) dot_seg<R>(sWt, sH2, jt, 0, klo0, khi0, a);

        if constexpr (NSEG > 1) {
            CP_WAIT(0);
            __syncthreads();
            if (act) dot_seg<R>(sWt, sH2, jt, L0, klo1, khi1, a);
        }

        // ---- store partials ----
        if (act) {
            ulonglong2* rp = (ulonglong2*)sRed + ((size_t)s * R + jt) * 4;
            rp[0] = make_ulonglong2(a[0], a[1]); rp[1] = make_ulonglong2(a[2], a[3]);
            rp[2] = make_ulonglong2(a[4], a[5]); rp[3] = make_ulonglong2(a[6], a[7]);
        }
        __syncthreads();

        // ---- reduce across S + state update (h only; d_out deferred) ----
        if (upd) {
            unsigned long long x0 = 0, x1 = 0, y0 = 0, y1 = 0;
            const ulonglong2* rp = (const ulonglong2*)sRed + (size_t)jr * 4 + q;
            #pragma unroll
            for (int ss = 0; ss + 1 < S; ss += 2) {
                ulonglong2 v0 = rp[(size_t)ss * R * 4];
                ulonglong2 v1 = rp[(size_t)(ss + 1) * R * 4];
                ADD2(x0, v0.x); ADD2(y0, v0.y);
                ADD2(x1, v1.x); ADD2(y1, v1.y);
            }
            if constexpr (S & 1) {
                ulonglong2 v0 = rp[(size_t)(S - 1) * R * 4];
                ADD2(x0, v0.x); ADD2(y0, v0.y);
            }
            ADD2(x0, x1); ADD2(y0, y1);
            float ac[4];
            UNPK2(ac[0], ac[1], x0); UNPK2(ac[2], ac[3], y0);
            float w0 = 0.f, w1 = 0.f, w2 = 0.f, w3 = 0.f;
            if (RG == 0) { w0 = sWi[jr*4]; w1 = sWi[jr*4+1]; w2 = sWi[jr*4+2]; w3 = sWi[jr*4+3]; }
            float* hp = &hown.x;
            #pragma unroll
            for (int i2 = 0; i2 < 4; i2++) {
                const int b = q * 4 + i2;
                float d = sInh[jr * 16 + b] + tonic;
                if (RG == 0)
                    d += w0 * sInp[b*4] + w1 * sInp[b*4+1] + w2 * sInp[b*4+2] + w3 * sInp[b*4+3];
                float v = hp[i2] * (1.f - DTC) + DTC * (ac[i2] + d);
                hp[i2] = fmaxf(v, 0.f);
            }
            __stcg((float4*)(g_h[(t + 1) & 7] + (size_t)jg_u * 16) + q, hown);
        }
        __syncthreads();
        // single fence + publish on this CTA's counter
        if (tid == 0) { __threadfence(); red_rel(&g_cnt[pub * 128]); }

        // ---- deferred d_out writes (off the inter-region critical path) ----
        if (upd) {
            const float* hp = &hown.x;
            #pragma unroll
            for (int i2 = 0; i2 < 4; i2++) {
                const int b = q * 4 + i2;
                d_out[RNN_OFF + ((size_t)b * TT + t) * H6 + jg_u] = hp[i2];
                if (t == TT - 1) d_out[HN_OFF + (size_t)b * H6 + jg_u] = hp[i2];
            }
        }
    }
}

__global__ void __launch_bounds__(NTHR, 1) rnn_persist(
    const float* __restrict__ inp, const float* __restrict__ inhib,
    const float* __restrict__ inp_w, float* __restrict__ d_out)
{
    extern __shared__ float sm[];
    const int b = blockIdx.x;
    //            RG  R   S    K  NSEG C0A C0B S0  W0   L0  C1 S1  W1   L1  C2 S2  W2   L2
    if (b < 32) {       // str rows 128..383: seg0=str(self), then thal, alm
        run_region<0,  8, 32, 1408, 3,  0, 6,  0, 0, 512,  4, 4, 512, 512,  5, 5, 1024, 384>(
            128 + b * 8, (b < 16) ? 0 : 6, inp, inhib, inp_w, d_out, sm);
    } else if (b < 48) { // str rows 0..127 & 384..511: seg0=str(self), then alm
        int c = b - 32;
        int j0 = (c < 8) ? c * 16 : 384 + (c - 8) * 16;
        run_region<0, 16, 16,  896, 2,  0, 6,  0, 0, 512,  5, 5, 1024, 384,  0, 0, 0, 0>(
            j0, (c < 8) ? 0 : 6, inp, inhib, inp_w, d_out, sm);
    } else if (b < 56) { // gpe: needs only str rows 256-511 -> counter 6
        run_region<1, 64,  4,  256, 1,  6, 99, 0, 256, 256,  0, 0, 0, 0,  0, 0, 0, 0>(
            (b - 48) * 64, 1, inp, inhib, inp_w, d_out, sm);
    } else if (b < 72) { // stn (gpe)
        run_region<2, 32,  8,  512, 1,  1, 99, 1, 0, 512,  0, 0, 0, 0,  0, 0, 0, 0>(
            (b - 56) * 32, 2, inp, inhib, inp_w, d_out, sm);
    } else if (b < 100) { // snr: needs only str rows 0-255 -> counter 0; then stn
        run_region<3, 19, 13,  768, 2,  0, 99, 0, 0, 256,  2, 2, 512, 512,  0, 0, 0, 0>(
            (b - 72) * 19, 3, inp, inhib, inp_w, d_out, sm);
    } else if (b < 116) { // thal (snr)
        run_region<4, 32,  8,  512, 1,  3, 99, 3, 0, 512,  0, 0, 0, 0,  0, 0, 0, 0>(
            (b - 100) * 32, 4, inp, inhib, inp_w, d_out, sm);
    } else {             // alm: seg0=alm(self), then thal
        run_region<5, 16, 16, 1024, 2,  5, 99, 5, 512, 512,  4, 4, 0, 512,  0, 0, 0, 0>(
            (b - 116) * 16, 5, inp, inhib, inp_w, d_out, sm);
    }
}

// ---------------- epilogue: out = sigmoid(alm_h . v) ---------------------
__global__ void out_kernel(float* __restrict__ d_out)
{
    int gw   = (blockIdx.x * blockDim.x + threadIdx.x) >> 5;
    int lane = threadIdx.x & 31;
    if (gw >= BB * TT) return;
    const float4* row4 = (const float4*)(d_out + RNN_OFF + (size_t)gw * H6 + 5 * HID);
    const float4* v4   = (const float4*)g_v;
    float sum = 0.f;
    #pragma unroll
    for (int j = lane; j < 128; j += 32) {
        float4 rv = row4[j], vv = v4[j];
        sum = fmaf(rv.x, vv.x, fmaf(rv.y, vv.y, fmaf(rv.z, vv.z, fmaf(rv.w, vv.w, sum))));
    }
    #pragma unroll
    for (int o = 16; o; o >>= 1) sum += __shfl_xor_sync(0xffffffffu, sum, o);
    if (lane == 0) d_out[gw] = 1.f / (1.f + expf(-sum));
}

// ---------------- epilogue: x_out / x_last broadcast copy ----------------
__global__ void x_kernel(const float* __restrict__ x, float* __restrict__ d_out)
{
    const float4* x4 = (const float4*)x;
    float4* o4 = (float4*)d_out;
    const size_t total = 12288 + 12288000;
    for (size_t i = blockIdx.x * (size_t)blockDim.x + threadIdx.x; i < total;
         i += (size_t)gridDim.x * blockDim.x) {
        if (i < 12288) {
            o4[XLAST_OFF / 4 + i] = x4[i];
        } else {
            size_t e = i - 12288;
            int j4 = (int)(e % 768);
            int bt = (int)(e / 768);
            int bq = bt / TT;
            o4[XOUT_OFF / 4 + e] = x4[bq * 768 + j4];
        }
    }
}

extern "C" void kernel_launch(void* const* d_in, const int* in_sizes, int n_in,
                              void* d_out_v, int out_size)
{
    const float* inp        = (const float*)d_in[0];
    const float* hn         = (const float*)d_in[1];
    const float* x          = (const float*)d_in[2];
    const float* inhib      = (const float*)d_in[3];
    const float* thal2alm_w = (const float*)d_in[5];
    const float* thal2str_w = (const float*)d_in[6];
    const float* alm2alm_w  = (const float*)d_in[7];
    const float* alm2str_w  = (const float*)d_in[8];
    const float* str2snr_w  = (const float*)d_in[9];
    const float* str2gpe_w  = (const float*)d_in[10];
    const float* gpe2stn_w  = (const float*)d_in[11];
    const float* stn2snr_w  = (const float*)d_in[12];
    const float* snr2thal_w = (const float*)d_in[13];
    const float* inp_w      = (const float*)d_in[14];
    const float* fc1        = (const float*)d_in[15];
    const float* fc2        = (const float*)d_in[16];
    const float* fixed      = (const float*)d_in[17];
    float* d_out = (float*)d_out_v;

    // max smem: str-A = 45056 + 90112 + 32768 + 512 + 128 + 256 = 168832 B
    static int smem_set = 0;
    if (!smem_set) {
        cudaFuncSetAttribute(rnn_persist, cudaFuncAttributeMaxDynamicSharedMemorySize, 172032);
        smem_set = 1;
    }

    // x_kernel first: independent of the RNN, overlaps prep
    x_kernel<<<4096, 256>>>(x, d_out);

    int prep_total = W_TOT + H6 * BB + HID;
    prep_kernel<<<(prep_total + 255) / 256, 256>>>(
        hn, thal2alm_w, thal2str_w, alm2alm_w, alm2str_w, str2snr_w,
        str2gpe_w, gpe2stn_w, stn2snr_w, snr2thal_w, fc1, fc2, fixed);

    rnn_persist<<<NCTA, NTHR, 172032>>>(inp, inhib, inp_w, d_out);

    out_kernel<<<(BB * TT * 32 + 255) / 256, 256>>>(d_out);
}